// round 12
// baseline (speedup 1.0000x reference)
#include <cuda_runtime.h>
#include <cuda_fp16.h>

// HawkesKT — table-collapsed; fp16 table in GMEM, fp32-expanded in SMEM at gather time.
// Table entry (GMEM): half2(ga, d) with d = -(beta-1)/ln5.
// SMEM entry: float2(ga, gb) with gb = d - 1/ln5 = -beta/ln5.
// Inner: sum_{i<j} ga * 2^(gb * log2(max(|ti-tj|, 1e-10)))   (1 LG2 + 1 EX2 per pair)

#define NJ  16         // j-columns per CTA
#define RSJ 513        // Gs row stride in float2 units (odd: LDS.64 banks 2(tj+e) mod 32, conflict-free)

__device__ __half2 g_pack[256 * 512];   // [c][e] -> (ga, d)

__device__ __forceinline__ float fast_ex2(float x) {
    float r;
    asm("ex2.approx.f32 %0, %1;" : "=f"(r) : "f"(x));
    return r;
}

// ---------------- Precompute: dual 512x256x64 GEMM into packed fp16 table (128 CTAs) ----------------
__global__ __launch_bounds__(256)
void precompute_kernel(const float* __restrict__ a_inter,    // [512,64]
                       const float* __restrict__ a_concept,  // [256,64]
                       const float* __restrict__ b_inter,    // [512,64]
                       const float* __restrict__ b_concept)  // [256,64]
{
    __shared__ float4 ai[4][16], bi[4][16];   // [e_local][d4]
    const int e0  = blockIdx.x * 4;
    const int tid = threadIdx.x;
    if (tid < 64) {
        ai[tid >> 4][tid & 15] = ((const float4*)a_inter)[(e0 + (tid >> 4)) * 16 + (tid & 15)];
    } else if (tid < 128) {
        int t = tid - 64;
        bi[t >> 4][t & 15] = ((const float4*)b_inter)[(e0 + (t >> 4)) * 16 + (t & 15)];
    }
    __syncthreads();

    const int c = tid;
    float acc_a[4] = {0.f, 0.f, 0.f, 0.f};
    float acc_b[4] = {0.f, 0.f, 0.f, 0.f};

    #pragma unroll
    for (int d4 = 0; d4 < 16; d4++) {
        float4 av = ((const float4*)a_concept)[c * 16 + d4];
        float4 bv = ((const float4*)b_concept)[c * 16 + d4];
        #pragma unroll
        for (int e = 0; e < 4; e++) {
            float4 u = ai[e][d4];
            float4 w = bi[e][d4];
            acc_a[e] = fmaf(av.x, u.x, fmaf(av.y, u.y, fmaf(av.z, u.z, fmaf(av.w, u.w, acc_a[e]))));
            acc_b[e] = fmaf(bv.x, w.x, fmaf(bv.y, w.y, fmaf(bv.z, w.z, fmaf(bv.w, w.w, acc_b[e]))));
        }
    }
    #pragma unroll
    for (int e = 0; e < 4; e++) {
        float beta = fminf(fmaxf(acc_b[e] + 1.0f, 0.0f), 10.0f);
        float d    = -0.62133497f * (beta - 1.0f);   // small delta -> fp16-safe
        g_pack[c * 512 + e0 + e] = __floats2half2_rn(acc_a[e], d);
    }
}

// ---------------- Main: causal elementwise sum ----------------
__global__ __launch_bounds__(256)
void hawkes_main(const int* __restrict__ concept_seq,      // [32,1024]
                 const int* __restrict__ question_seq,     // [32,1024]
                 const int* __restrict__ correctness_seq,  // [32,1024]
                 const int* __restrict__ time_seq,         // [32,1024]
                 const float* __restrict__ q_bias,         // [10000]
                 const float* __restrict__ c_bias,         // [256]
                 float* __restrict__ out)                  // [32,1023]
{
    constexpr int SEQ = 1024;
    const float C0 = 0.62133497f;                  // 1/ln5

    extern __shared__ unsigned char smraw[];
    float2* Gs   = (float2*)smraw;                 // [NJ][RSJ] -> (ga, gb) fp32
    float2* tse  = (float2*)(smraw + NJ * RSJ * 8);// [<=1024] (time, e*8 as int bits)
    float*  jred = (float*)(tse + SEQ);            // [NJ]

    const int b   = blockIdx.y;
    const int j0  = ((int)gridDim.x - 1 - (int)blockIdx.x) * NJ;  // big tiles first
    const int tid = threadIdx.x;
    const int tj  = tid & (NJ - 1);                // 0..15
    const int si  = tid >> 4;                      // 0..15
    const int iend = j0 + NJ;

    // Stage (time, e*8 byte offset) for the i-range this CTA consumes
    for (int i = tid; i < iend; i += 256) {
        int g = b * SEQ + i;
        int e = concept_seq[g] + (correctness_seq[g] << 8);
        tse[i] = make_float2((float)time_seq[g], __int_as_float(e * 8));
    }
    if (tid < NJ) jred[tid] = 0.0f;

    // Gather + fp32-expand: Gs[jl][e] <- cvt(g_pack[c_j][e]), gb = d - C0
    for (int idx = tid; idx < NJ * 128; idx += 256) {
        int jl = idx >> 7;               // 0..15
        int q  = idx & 127;              // uint4 index (4 half2 entries at e=4q)
        int cj = __ldg(concept_seq + b * SEQ + j0 + jl);
        uint4 v = ((const uint4*)(g_pack + cj * 512))[q];
        float2* dst = Gs + jl * RSJ + 4 * q;
        float2 f0 = __half22float2(*(__half2*)&v.x);
        float2 f1 = __half22float2(*(__half2*)&v.y);
        float2 f2 = __half22float2(*(__half2*)&v.z);
        float2 f3 = __half22float2(*(__half2*)&v.w);
        dst[0] = make_float2(f0.x, f0.y - C0);
        dst[1] = make_float2(f1.x, f1.y - C0);
        dst[2] = make_float2(f2.x, f2.y - C0);
        dst[3] = make_float2(f3.x, f3.y - C0);
    }
    __syncthreads();

    const int   jg   = j0 + tj;
    const float tjv  = tse[jg].x;
    const char* Grow = (const char*)(Gs + tj * RSJ);
    float jsum0 = 0.0f, jsum1 = 0.0f;

    // ---- Main region: i in [0, I0), no causal mask (I0 <= j0 <= jg) ----
    const int I0 = j0 & ~31;                        // multiple of 32
    const float4* tse4 = (const float4*)tse;        // pairs of (t, e8)
    const int kend = I0 >> 5;                       // each k covers i = 32k + 2si + {0,1}

    #pragma unroll 4
    for (int k = 0; k < kend; k++) {
        float4 tp = tse4[k * 16 + si];              // LDS.128
        float2 g0 = *(const float2*)(Grow + __float_as_int(tp.y));   // LDS.64
        float2 g1 = *(const float2*)(Grow + __float_as_int(tp.w));
        float lg0 = __log2f(fmaxf(fabsf(tp.x - tjv), 1e-10f));
        float lg1 = __log2f(fmaxf(fabsf(tp.z - tjv), 1e-10f));
        jsum0 = fmaf(g0.x, fast_ex2(g0.y * lg0), jsum0);
        jsum1 = fmaf(g1.x, fast_ex2(g1.y * lg1), jsum1);
    }

    // ---- Tail: i in [I0, iend), masked i < jg (<= 2 iterations) ----
    for (int i = I0 + si; i < iend; i += 16) {
        float2 tv = tse[i];
        float2 g  = *(const float2*)(Grow + __float_as_int(tv.y));
        float lg  = __log2f(fmaxf(fabsf(tv.x - tjv), 1e-10f));
        float ex  = fast_ex2(g.y * lg);
        jsum0 += (i < jg) ? g.x * ex : 0.0f;
    }

    // Reduce si slots -> per-j (warp has 2 si-groups of 16 lanes)
    float jsum = jsum0 + jsum1;
    jsum += __shfl_down_sync(0xffffffffu, jsum, 16);
    if ((tid & 31) < NJ) atomicAdd(&jred[tj], jsum);
    __syncthreads();

    // Epilogue: bias + sigmoid; output drops j=0
    if (tid < NJ) {
        int j = j0 + tid;
        if (j > 0) {
            float x = q_bias[question_seq[b * SEQ + j]]
                    + c_bias[concept_seq[b * SEQ + j]]
                    + jred[tid];
            out[b * (SEQ - 1) + (j - 1)] = 1.0f / (1.0f + __expf(-x));
        }
    }
}

extern "C" void kernel_launch(void* const* d_in, const int* in_sizes, int n_in,
                              void* d_out, int out_size)
{
    (void)in_sizes; (void)n_in; (void)out_size;
    const int*   concept_seq     = (const int*)  d_in[0];
    const int*   question_seq    = (const int*)  d_in[1];
    const int*   correctness_seq = (const int*)  d_in[2];
    const int*   time_seq        = (const int*)  d_in[3];
    const float* a_inter         = (const float*)d_in[4];
    const float* a_concept       = (const float*)d_in[5];
    const float* b_inter         = (const float*)d_in[6];
    const float* b_concept       = (const float*)d_in[7];
    const float* q_bias          = (const float*)d_in[8];
    const float* c_bias          = (const float*)d_in[9];
    float* out = (float*)d_out;

    precompute_kernel<<<128, 256>>>(a_inter, a_concept, b_inter, b_concept);

    const int smem_bytes = NJ * RSJ * 8 + 1024 * 8 + NJ * 4;   // 73,920 B -> 3 CTAs/SM
    cudaFuncSetAttribute(hawkes_main,
                         cudaFuncAttributeMaxDynamicSharedMemorySize, smem_bytes);
    dim3 grid(1024 / NJ, 32);   // (j-tiles, batches)
    hawkes_main<<<grid, 256, smem_bytes>>>(
        concept_seq, question_seq, correctness_seq, time_seq,
        q_bias, c_bias, out);
}

// round 14
// speedup vs baseline: 1.8700x; 1.8700x over previous
#include <cuda_runtime.h>
#include <cuda_fp16.h>

// HawkesKT — table-collapsed, fp16-packed table, NJ=32 / 512-thread CTAs.
// Table entry: half2(ga, d) with d = -(beta-1)/ln5.
// Inner: sum_{i<j} ga * 2^((d - 1/ln5) * log2(|ti-tj| + 1e-10))   (1 LG2 + 1 EX2 per pair)

#define NJ  32         // j-columns per CTA
#define RSJ 515        // Gs row stride in half2 units: bank=(3*tj+e)%32, conflict-free
#define THREADS 512

__device__ __half2 g_pack[256 * 512];   // [c][e] -> (ga, d)

__device__ __forceinline__ float fast_ex2(float x) {
    float r;
    asm("ex2.approx.f32 %0, %1;" : "=f"(r) : "f"(x));
    return r;
}

// ---------------- Precompute: dual 512x256x64 GEMM into packed fp16 table (128 CTAs) ----------------
__global__ __launch_bounds__(256)
void precompute_kernel(const float* __restrict__ a_inter,    // [512,64]
                       const float* __restrict__ a_concept,  // [256,64]
                       const float* __restrict__ b_inter,    // [512,64]
                       const float* __restrict__ b_concept)  // [256,64]
{
    __shared__ float4 ai[4][16], bi[4][16];   // [e_local][d4]
    const int e0  = blockIdx.x * 4;
    const int tid = threadIdx.x;
    if (tid < 64) {
        ai[tid >> 4][tid & 15] = ((const float4*)a_inter)[(e0 + (tid >> 4)) * 16 + (tid & 15)];
    } else if (tid < 128) {
        int t = tid - 64;
        bi[t >> 4][t & 15] = ((const float4*)b_inter)[(e0 + (t >> 4)) * 16 + (t & 15)];
    }
    __syncthreads();

    const int c = tid;
    float acc_a[4] = {0.f, 0.f, 0.f, 0.f};
    float acc_b[4] = {0.f, 0.f, 0.f, 0.f};

    #pragma unroll
    for (int d4 = 0; d4 < 16; d4++) {
        float4 av = ((const float4*)a_concept)[c * 16 + d4];
        float4 bv = ((const float4*)b_concept)[c * 16 + d4];
        #pragma unroll
        for (int e = 0; e < 4; e++) {
            float4 u = ai[e][d4];
            float4 w = bi[e][d4];
            acc_a[e] = fmaf(av.x, u.x, fmaf(av.y, u.y, fmaf(av.z, u.z, fmaf(av.w, u.w, acc_a[e]))));
            acc_b[e] = fmaf(bv.x, w.x, fmaf(bv.y, w.y, fmaf(bv.z, w.z, fmaf(bv.w, w.w, acc_b[e]))));
        }
    }
    #pragma unroll
    for (int e = 0; e < 4; e++) {
        float beta = fminf(fmaxf(acc_b[e] + 1.0f, 0.0f), 10.0f);
        float d    = -0.62133497f * (beta - 1.0f);   // small delta -> fp16-safe
        g_pack[c * 512 + e0 + e] = __floats2half2_rn(acc_a[e], d);
    }
}

// ---------------- Main: causal elementwise sum ----------------
__global__ __launch_bounds__(THREADS, 3)
void hawkes_main(const int* __restrict__ concept_seq,      // [32,1024]
                 const int* __restrict__ question_seq,     // [32,1024]
                 const int* __restrict__ correctness_seq,  // [32,1024]
                 const int* __restrict__ time_seq,         // [32,1024]
                 const float* __restrict__ q_bias,         // [10000]
                 const float* __restrict__ c_bias,         // [256]
                 float* __restrict__ out)                  // [32,1023]
{
    constexpr int SEQ = 1024;
    const float C0 = 0.62133497f;                  // 1/ln5

    extern __shared__ unsigned char smraw[];
    __half2* Gs  = (__half2*)smraw;                // [NJ][RSJ]
    float2*  tse = (float2*)(smraw + NJ * RSJ * 4);// [<=1024] (time, e*4 as int bits)
    float*  jred = (float*)(tse + SEQ);            // [NJ]

    const int b   = blockIdx.y;
    const int j0  = ((int)gridDim.x - 1 - (int)blockIdx.x) * NJ;  // big tiles first
    const int tid = threadIdx.x;
    const int tj  = tid & (NJ - 1);                // 0..31  (warp lane)
    const int si  = tid >> 5;                      // 0..15  (uniform per warp)
    const int iend = j0 + NJ;

    // Stage (time, e*4 byte offset) for the i-range this CTA consumes
    for (int i = tid; i < iend; i += THREADS) {
        int g = b * SEQ + i;
        int e = concept_seq[g] + (correctness_seq[g] << 8);
        tse[i] = make_float2((float)time_seq[g], __int_as_float(e * 4));
    }
    if (tid < NJ) jred[tid] = 0.0f;

    // Gather packed rows: Gs[jl][e] <- g_pack[c_j][e]  (LDG.128 = 4 half2 entries)
    for (int idx = tid; idx < NJ * 128; idx += THREADS) {
        int jl = idx >> 7;               // 0..31
        int q  = idx & 127;              // uint4 index (4 half2 entries at e=4q)
        int cj = __ldg(concept_seq + b * SEQ + j0 + jl);
        uint4 v = ((const uint4*)(g_pack + cj * 512))[q];
        __half2* dst = Gs + jl * RSJ + 4 * q;
        dst[0] = *(__half2*)&v.x;  dst[1] = *(__half2*)&v.y;
        dst[2] = *(__half2*)&v.z;  dst[3] = *(__half2*)&v.w;
    }
    __syncthreads();

    const int   jg   = j0 + tj;
    const float tjv  = tse[jg].x;
    const char* Grow = (const char*)(Gs + tj * RSJ);
    float jsum0 = 0.0f, jsum1 = 0.0f;

    // ---- Main region: i in [0, I0), no causal mask (I0 <= j0 <= jg) ----
    const int I0 = j0 & ~31;                        // multiple of 32
    const float4* tse4 = (const float4*)tse;        // pairs of (t, e4)
    const int kend = I0 >> 5;                       // each k covers i = 32k + 2si + {0,1}

    #pragma unroll 4
    for (int k = 0; k < kend; k++) {
        float4 tp = tse4[k * 16 + si];              // LDS.128, full-warp broadcast
        float2 g0 = __half22float2(*(const __half2*)(Grow + __float_as_int(tp.y)));
        float2 g1 = __half22float2(*(const __half2*)(Grow + __float_as_int(tp.w)));
        float lg0 = __log2f(fabsf(tp.x - tjv) + 1e-10f);
        float lg1 = __log2f(fabsf(tp.z - tjv) + 1e-10f);
        float a0  = fmaf(g0.y, lg0, -C0 * lg0);     // (d - C0) * lg
        float a1  = fmaf(g1.y, lg1, -C0 * lg1);
        jsum0 = fmaf(g0.x, fast_ex2(a0), jsum0);
        jsum1 = fmaf(g1.x, fast_ex2(a1), jsum1);
    }

    // ---- Tail: i in [I0, iend), masked i < jg (<= 64 i's -> <= 4 iterations) ----
    for (int i = I0 + si; i < iend; i += 16) {
        float2 tv = tse[i];
        float2 g  = __half22float2(*(const __half2*)(Grow + __float_as_int(tv.y)));
        float lg  = __log2f(fabsf(tv.x - tjv) + 1e-10f);
        float ex  = fast_ex2(fmaf(g.y, lg, -C0 * lg));
        jsum0 += (i < jg) ? g.x * ex : 0.0f;
    }

    // Every lane owns a distinct tj within its warp -> spread smem atomics
    atomicAdd(&jred[tj], jsum0 + jsum1);
    __syncthreads();

    // Epilogue: bias + sigmoid; output drops j=0
    if (tid < NJ) {
        int j = j0 + tid;
        if (j > 0) {
            float x = q_bias[question_seq[b * SEQ + j]]
                    + c_bias[concept_seq[b * SEQ + j]]
                    + jred[tid];
            out[b * (SEQ - 1) + (j - 1)] = 1.0f / (1.0f + __expf(-x));
        }
    }
}

extern "C" void kernel_launch(void* const* d_in, const int* in_sizes, int n_in,
                              void* d_out, int out_size)
{
    (void)in_sizes; (void)n_in; (void)out_size;
    const int*   concept_seq     = (const int*)  d_in[0];
    const int*   question_seq    = (const int*)  d_in[1];
    const int*   correctness_seq = (const int*)  d_in[2];
    const int*   time_seq        = (const int*)  d_in[3];
    const float* a_inter         = (const float*)d_in[4];
    const float* a_concept       = (const float*)d_in[5];
    const float* b_inter         = (const float*)d_in[6];
    const float* b_concept       = (const float*)d_in[7];
    const float* q_bias          = (const float*)d_in[8];
    const float* c_bias          = (const float*)d_in[9];
    float* out = (float*)d_out;

    precompute_kernel<<<128, 256>>>(a_inter, a_concept, b_inter, b_concept);

    const int smem_bytes = NJ * RSJ * 4 + 1024 * 8 + NJ * 4;   // 74,240 B -> 3 CTAs/SM
    cudaFuncSetAttribute(hawkes_main,
                         cudaFuncAttributeMaxDynamicSharedMemorySize, smem_bytes);
    dim3 grid(1024 / NJ, 32);   // (j-tiles, batches) = (32, 32)
    hawkes_main<<<grid, THREADS, smem_bytes>>>(
        concept_seq, question_seq, correctness_seq, time_seq,
        q_bias, c_bias, out);
}

// round 15
// speedup vs baseline: 1.9290x; 1.0316x over previous
#include <cuda_runtime.h>
#include <cuda_fp16.h>

// HawkesKT — table-collapsed, fp16-packed table, NJ=32 / 512-thread CTAs.
// Table entry: half2(ga, d) with d = -(beta-1)/ln5.
// Inner: sum_{i<j} ga * 2^((d - 1/ln5) * log2(|ti-tj| + 1e-10))   (1 LG2 + 1 EX2 per pair)

#define NJ  32         // j-columns per CTA
#define RSJ 515        // Gs row stride in half2 units: bank=(3*tj+e)%32, conflict-free
#define THREADS 512

__device__ __half2 g_pack[256 * 512];   // [c][e] -> (ga, d)

__device__ __forceinline__ float fast_ex2(float x) {
    float r;
    asm("ex2.approx.f32 %0, %1;" : "=f"(r) : "f"(x));
    return r;
}

// ---------------- Precompute: coalesced shuffle-GEMV into packed fp16 table ----------------
// 128 CTAs x 256 thr. CTA owns 4 e-rows. Lanes split the 64-dim dot: d4 = tid&15
// (one float4 each), c-pairs walk 16 concepts per pass with fully coalesced LDG.128.
__global__ __launch_bounds__(256)
void precompute_kernel(const float* __restrict__ a_inter,    // [512,64]
                       const float* __restrict__ a_concept,  // [256,64]
                       const float* __restrict__ b_inter,    // [512,64]
                       const float* __restrict__ b_concept)  // [256,64]
{
    const int e0 = blockIdx.x * 4;
    const int tid = threadIdx.x;
    const int d4 = tid & 15;       // which float4 of the 64-dim row
    const int cl = tid >> 4;       // c_local 0..15

    float4 ai_r[4], bi_r[4];       // this lane's slice of the 4 e-rows
    #pragma unroll
    for (int e = 0; e < 4; e++) {
        ai_r[e] = ((const float4*)a_inter)[(e0 + e) * 16 + d4];
        bi_r[e] = ((const float4*)b_inter)[(e0 + e) * 16 + d4];
    }

    for (int p = 0; p < 16; p++) {
        int c = p * 16 + cl;
        float4 av = ((const float4*)a_concept)[c * 16 + d4];   // warp: 2 contiguous rows
        float4 bv = ((const float4*)b_concept)[c * 16 + d4];

        float pa[4], pb[4];
        #pragma unroll
        for (int e = 0; e < 4; e++) {
            pa[e] = fmaf(av.x, ai_r[e].x, fmaf(av.y, ai_r[e].y,
                    fmaf(av.z, ai_r[e].z, av.w * ai_r[e].w)));
            pb[e] = fmaf(bv.x, bi_r[e].x, fmaf(bv.y, bi_r[e].y,
                    fmaf(bv.z, bi_r[e].z, bv.w * bi_r[e].w)));
        }
        // Reduce over the 16 d4-lanes (segments of 16)
        #pragma unroll
        for (int m = 1; m < 16; m <<= 1) {
            #pragma unroll
            for (int e = 0; e < 4; e++) {
                pa[e] += __shfl_xor_sync(0xffffffffu, pa[e], m, 16);
                pb[e] += __shfl_xor_sync(0xffffffffu, pb[e], m, 16);
            }
        }
        if (d4 == 0) {
            #pragma unroll
            for (int e = 0; e < 4; e++) {
                float beta = fminf(fmaxf(pb[e] + 1.0f, 0.0f), 10.0f);
                float d    = -0.62133497f * (beta - 1.0f);   // small delta -> fp16-safe
                g_pack[c * 512 + e0 + e] = __floats2half2_rn(pa[e], d);
            }
        }
    }
}

// ---------------- Main: causal elementwise sum ----------------
__global__ __launch_bounds__(THREADS, 3)
void hawkes_main(const int* __restrict__ concept_seq,      // [32,1024]
                 const int* __restrict__ question_seq,     // [32,1024]
                 const int* __restrict__ correctness_seq,  // [32,1024]
                 const int* __restrict__ time_seq,         // [32,1024]
                 const float* __restrict__ q_bias,         // [10000]
                 const float* __restrict__ c_bias,         // [256]
                 float* __restrict__ out)                  // [32,1023]
{
    constexpr int SEQ = 1024;
    const float C0 = 0.62133497f;                  // 1/ln5

    extern __shared__ unsigned char smraw[];
    __half2* Gs  = (__half2*)smraw;                // [NJ][RSJ]
    float2*  tse = (float2*)(smraw + NJ * RSJ * 4);// [<=1024] (time, e*4 as int bits)
    float*  jred = (float*)(tse + SEQ);            // [NJ]

    const int b   = blockIdx.y;
    const int j0  = ((int)gridDim.x - 1 - (int)blockIdx.x) * NJ;  // big tiles first
    const int tid = threadIdx.x;
    const int tj  = tid & (NJ - 1);                // 0..31  (warp lane)
    const int si  = tid >> 5;                      // 0..15  (uniform per warp)
    const int iend = j0 + NJ;

    // Stage (time, e*4 byte offset) for the i-range this CTA consumes
    for (int i = tid; i < iend; i += THREADS) {
        int g = b * SEQ + i;
        int e = concept_seq[g] + (correctness_seq[g] << 8);
        tse[i] = make_float2((float)time_seq[g], __int_as_float(e * 4));
    }
    if (tid < NJ) jred[tid] = 0.0f;

    // Gather packed rows: Gs[jl][e] <- g_pack[c_j][e]  (LDG.128 = 4 half2 entries)
    for (int idx = tid; idx < NJ * 128; idx += THREADS) {
        int jl = idx >> 7;               // 0..31
        int q  = idx & 127;              // uint4 index (4 half2 entries at e=4q)
        int cj = __ldg(concept_seq + b * SEQ + j0 + jl);
        uint4 v = ((const uint4*)(g_pack + cj * 512))[q];
        __half2* dst = Gs + jl * RSJ + 4 * q;
        dst[0] = *(__half2*)&v.x;  dst[1] = *(__half2*)&v.y;
        dst[2] = *(__half2*)&v.z;  dst[3] = *(__half2*)&v.w;
    }
    __syncthreads();

    const int   jg   = j0 + tj;
    const float tjv  = tse[jg].x;
    const char* Grow = (const char*)(Gs + tj * RSJ);
    float jsum0 = 0.0f, jsum1 = 0.0f;

    // ---- Main region: i in [0, I0), no causal mask (I0 <= j0 <= jg) ----
    const int I0 = j0 & ~31;                        // multiple of 32
    const float4* tse4 = (const float4*)tse;        // pairs of (t, e4)
    const int kend = I0 >> 5;                       // each k covers i = 32k + 2si + {0,1}

    #pragma unroll 4
    for (int k = 0; k < kend; k++) {
        float4 tp = tse4[k * 16 + si];              // LDS.128, full-warp broadcast
        float2 g0 = __half22float2(*(const __half2*)(Grow + __float_as_int(tp.y)));
        float2 g1 = __half22float2(*(const __half2*)(Grow + __float_as_int(tp.w)));
        float lg0 = __log2f(fabsf(tp.x - tjv) + 1e-10f);
        float lg1 = __log2f(fabsf(tp.z - tjv) + 1e-10f);
        float a0  = fmaf(g0.y, lg0, -C0 * lg0);     // (d - C0) * lg
        float a1  = fmaf(g1.y, lg1, -C0 * lg1);
        jsum0 = fmaf(g0.x, fast_ex2(a0), jsum0);
        jsum1 = fmaf(g1.x, fast_ex2(a1), jsum1);
    }

    // ---- Tail: i in [I0, iend), masked i < jg (<= 64 i's -> <= 4 iterations) ----
    for (int i = I0 + si; i < iend; i += 16) {
        float2 tv = tse[i];
        float2 g  = __half22float2(*(const __half2*)(Grow + __float_as_int(tv.y)));
        float lg  = __log2f(fabsf(tv.x - tjv) + 1e-10f);
        float ex  = fast_ex2(fmaf(g.y, lg, -C0 * lg));
        jsum0 += (i < jg) ? g.x * ex : 0.0f;
    }

    // Every lane owns a distinct tj within its warp -> spread smem atomics
    atomicAdd(&jred[tj], jsum0 + jsum1);
    __syncthreads();

    // Epilogue: bias + sigmoid; output drops j=0
    if (tid < NJ) {
        int j = j0 + tid;
        if (j > 0) {
            float x = q_bias[question_seq[b * SEQ + j]]
                    + c_bias[concept_seq[b * SEQ + j]]
                    + jred[tid];
            out[b * (SEQ - 1) + (j - 1)] = 1.0f / (1.0f + __expf(-x));
        }
    }
}

extern "C" void kernel_launch(void* const* d_in, const int* in_sizes, int n_in,
                              void* d_out, int out_size)
{
    (void)in_sizes; (void)n_in; (void)out_size;
    const int*   concept_seq     = (const int*)  d_in[0];
    const int*   question_seq    = (const int*)  d_in[1];
    const int*   correctness_seq = (const int*)  d_in[2];
    const int*   time_seq        = (const int*)  d_in[3];
    const float* a_inter         = (const float*)d_in[4];
    const float* a_concept       = (const float*)d_in[5];
    const float* b_inter         = (const float*)d_in[6];
    const float* b_concept       = (const float*)d_in[7];
    const float* q_bias          = (const float*)d_in[8];
    const float* c_bias          = (const float*)d_in[9];
    float* out = (float*)d_out;

    precompute_kernel<<<128, 256>>>(a_inter, a_concept, b_inter, b_concept);

    const int smem_bytes = NJ * RSJ * 4 + 1024 * 8 + NJ * 4;   // 74,240 B -> 3 CTAs/SM
    cudaFuncSetAttribute(hawkes_main,
                         cudaFuncAttributeMaxDynamicSharedMemorySize, smem_bytes);
    dim3 grid(1024 / NJ, 32);   // (j-tiles, batches) = (32, 32)
    hawkes_main<<<grid, THREADS, smem_bytes>>>(
        concept_seq, question_seq, correctness_seq, time_seq,
        q_bias, c_bias, out);
}